// round 5
// baseline (speedup 1.0000x reference)
#include <cuda_runtime.h>
#include <cuda_bf16.h>

// class_logits [64,300,92] f32, pred_boxes [64,300,4] f32,
// tgt_labels [2048] i32, tgt_boxes [2048,4] f32  ->  out [64,300,2048] f32
#define BQ      19200   // 64*300
#define CC      92
#define PSTRIDE 96      // padded prob row stride (floats)
#define TT      2048
#define ROWS    16      // rows (queries) per block (one per warp)
#define NTHR    512
#define TPT     2       // targets per thread
#define TBLK    (NTHR * TPT)     // 1024 targets per block
#define GRIDX   (BQ / ROWS)      // 1200
#define GRIDY   (TT / TBLK)      // 2

__device__ __forceinline__ float frcp(float x) {
    float y;
    asm("rcp.approx.f32 %0, %1;" : "=f"(y) : "f"(x));
    return y;
}

__global__ __launch_bounds__(NTHR, 2)
void matcher_kernel(const float* __restrict__ logits,
                    const float* __restrict__ pboxes,
                    const int*   __restrict__ labels,
                    const float* __restrict__ tboxes,
                    float*       __restrict__ out)
{
    __shared__ float  s_prob[ROWS][PSTRIDE]; // 16 x 96 floats (holds 2 - prob)
    __shared__ float4 s_xy[ROWS];            // px0,py0,px1,py1
    __shared__ float4 s_cw[ROWS];            // pcx,pcy,pw,ph

    const int tid  = threadIdx.x;
    const int warp = tid >> 5;               // 0..15 -> softmax row
    const int lane = tid & 31;
    const int row0 = blockIdx.x * ROWS;

    // ---- Phase 1: per-row softmax (warp w -> row w); store (2 - prob) ----
    {
        const int rr = row0 + warp;
        const float* lrow = logits + (size_t)rr * CC;
        float l0 = lrow[lane];
        float l1 = lrow[lane + 32];
        float l2 = (lane + 64 < CC) ? lrow[lane + 64] : -1e30f;
        float m = fmaxf(l0, fmaxf(l1, l2));
        #pragma unroll
        for (int o = 16; o; o >>= 1) m = fmaxf(m, __shfl_xor_sync(0xffffffffu, m, o));
        float e0 = __expf(l0 - m);
        float e1 = __expf(l1 - m);
        float e2 = (lane + 64 < CC) ? __expf(l2 - m) : 0.0f;
        float s = e0 + e1 + e2;
        #pragma unroll
        for (int o = 16; o; o >>= 1) s += __shfl_xor_sync(0xffffffffu, s, o);
        float rinv = frcp(s);
        // s_prob holds (2 - prob): folds the "+2" of the giou rewrite AND the
        // class-cost sign into one gathered constant.
        s_prob[warp][lane]      = fmaf(-e0, rinv, 2.0f);
        s_prob[warp][lane + 32] = fmaf(-e1, rinv, 2.0f);
        if (lane + 64 < CC) s_prob[warp][lane + 64] = fmaf(-e2, rinv, 2.0f);

        if (lane == 0) {
            float4 pb = *(const float4*)(pboxes + (size_t)rr * 4);
            s_cw[warp] = pb;
            s_xy[warp] = make_float4(pb.x - 0.5f * pb.z, pb.y - 0.5f * pb.w,
                                     pb.x + 0.5f * pb.z, pb.y + 0.5f * pb.w);
        }
    }

    // ---- Phase 1b: this thread's 2 targets -> registers ----
    const int tbase = blockIdx.y * TBLK + tid * TPT;
    float tcx[TPT], tcy[TPT], tw[TPT], th[TPT];
    float tx0[TPT], ty0[TPT], tx1[TPT], ty1[TPT], ta[TPT];
    int lb[TPT];   // byte offsets into a prob row
    {
        int2 lv = *(const int2*)(labels + tbase);
        lb[0] = lv.x * 4; lb[1] = lv.y * 4;
    }
    #pragma unroll
    for (int j = 0; j < TPT; j++) {
        float4 tb = *(const float4*)(tboxes + (size_t)(tbase + j) * 4);
        tcx[j] = tb.x; tcy[j] = tb.y; tw[j] = tb.z; th[j] = tb.w;
        tx0[j] = tb.x - 0.5f * tb.z;
        ty0[j] = tb.y - 0.5f * tb.w;
        tx1[j] = tb.x + 0.5f * tb.z;
        ty1[j] = tb.y + 0.5f * tb.w;
        ta[j]  = tb.z * tb.w;
    }
    __syncthreads();

    // ---- Phase 2: 16 rows x 2 targets per thread ----
    // cost = 5*L1 - prob - 2*giou
    //      = 5*L1 + (2 - prob) - 2*inter/uni - 2*uni/ea
    const char* prow = (const char*)&s_prob[0][0];
    float* orow = out + (size_t)row0 * TT + tbase;
    #pragma unroll
    for (int r = 0; r < ROWS; r++) {
        const float4 xy = s_xy[r];          // LDS.128 broadcast
        const float4 cw = s_cw[r];          // LDS.128 broadcast
        const float px0 = xy.x, py0 = xy.y, px1 = xy.z, py1 = xy.w;
        const float pcx = cw.x, pcy = cw.y, pw = cw.z, ph = cw.w;
        const float pa  = pw * ph;

        float pr[TPT];
        #pragma unroll
        for (int j = 0; j < TPT; j++)
            pr[j] = *(const float*)(prow + lb[j]);   // = 2 - prob

        float res[TPT];
        #pragma unroll
        for (int j = 0; j < TPT; j++) {
            float l1d = fabsf(pcx - tcx[j]) + fabsf(pcy - tcy[j])
                      + fabsf(pw  - tw[j])  + fabsf(ph  - th[j]);
            float ex0 = fminf(px0, tx0[j]), ey0 = fminf(py0, ty0[j]);
            float ex1 = fmaxf(px1, tx1[j]), ey1 = fmaxf(py1, ty1[j]);
            float ew = ex1 - ex0;
            float eh = ey1 - ey0;
            float iw = fmaxf((pw + tw[j]) - ew, 0.0f);
            float ih = fmaxf((ph + th[j]) - eh, 0.0f);
            float inter = iw * ih;
            float ea    = ew * eh;
            float uni   = (pa + ta[j]) - inter;
            float t1    = inter * frcp(uni);
            float t2    = uni   * frcp(ea);
            res[j] = fmaf(-2.0f, t1, fmaf(-2.0f, t2, fmaf(5.0f, l1d, pr[j])));
        }
        *(float2*)orow = make_float2(res[0], res[1]);
        orow += TT;
        prow += PSTRIDE * sizeof(float);
    }
}

extern "C" void kernel_launch(void* const* d_in, const int* in_sizes, int n_in,
                              void* d_out, int out_size) {
    const float* logits = (const float*)d_in[0];
    const float* pboxes = (const float*)d_in[1];
    const int*   labels = (const int*)  d_in[2];
    const float* tboxes = (const float*)d_in[3];
    float* out = (float*)d_out;
    matcher_kernel<<<dim3(GRIDX, GRIDY), NTHR>>>(logits, pboxes, labels, tboxes, out);
}

// round 6
// speedup vs baseline: 1.0597x; 1.0597x over previous
#include <cuda_runtime.h>
#include <cuda_bf16.h>

// class_logits [64,300,92] f32, pred_boxes [64,300,4] f32,
// tgt_labels [2048] i32, tgt_boxes [2048,4] f32  ->  out [64,300,2048] f32
#define BQ      19200   // 64*300
#define CC      92
#define PSTRIDE 96      // padded prob row stride (floats)
#define TT      2048
#define ROWS    8       // rows (queries) per block (one per warp)
#define NTHR    256
#define TPT     4       // targets per thread
#define TBLK    (NTHR * TPT)     // 1024 targets per block
#define GRIDX   (BQ / ROWS)      // 2400
#define GRIDY   (TT / TBLK)      // 2

__device__ __forceinline__ float frcp(float x) {
    float y;
    asm("rcp.approx.f32 %0, %1;" : "=f"(y) : "f"(x));
    return y;
}

__global__ __launch_bounds__(NTHR, 4)
void matcher_kernel(const float* __restrict__ logits,
                    const float* __restrict__ pboxes,
                    const int*   __restrict__ labels,
                    const float* __restrict__ tboxes,
                    float*       __restrict__ out)
{
    __shared__ float  s_prob[ROWS][PSTRIDE]; // holds (2 - prob)
    __shared__ float4 s_cw[ROWS];            // pcx, pcy, pw/2, ph/2
    __shared__ float  s_pa[ROWS];            // pw*ph

    const int tid  = threadIdx.x;
    const int warp = tid >> 5;               // 0..7 -> softmax row
    const int lane = tid & 31;
    const int row0 = blockIdx.x * ROWS;

    // ---- Phase 1: per-row softmax (warp w -> row w); store (2 - prob) ----
    {
        const int rr = row0 + warp;
        const float* lrow = logits + (size_t)rr * CC;
        float l0 = lrow[lane];
        float l1 = lrow[lane + 32];
        float l2 = (lane + 64 < CC) ? lrow[lane + 64] : -1e30f;
        float m = fmaxf(l0, fmaxf(l1, l2));
        #pragma unroll
        for (int o = 16; o; o >>= 1) m = fmaxf(m, __shfl_xor_sync(0xffffffffu, m, o));
        float e0 = __expf(l0 - m);
        float e1 = __expf(l1 - m);
        float e2 = (lane + 64 < CC) ? __expf(l2 - m) : 0.0f;
        float s = e0 + e1 + e2;
        #pragma unroll
        for (int o = 16; o; o >>= 1) s += __shfl_xor_sync(0xffffffffu, s, o);
        float rinv = frcp(s);
        // (2 - prob): folds class-cost sign and the "+2" of the giou rewrite.
        s_prob[warp][lane]      = fmaf(-e0, rinv, 2.0f);
        s_prob[warp][lane + 32] = fmaf(-e1, rinv, 2.0f);
        if (lane + 64 < CC) s_prob[warp][lane + 64] = fmaf(-e2, rinv, 2.0f);

        if (lane == 0) {
            float4 pb = *(const float4*)(pboxes + (size_t)rr * 4);
            s_cw[warp] = make_float4(pb.x, pb.y, 0.5f * pb.z, 0.5f * pb.w);
            s_pa[warp] = pb.z * pb.w;
        }
    }

    // ---- Phase 1b: this thread's 4 targets -> registers (5 floats each) ----
    const int tbase = blockIdx.y * TBLK + tid * TPT;
    float tcx[TPT], tcy[TPT], tw2[TPT], th2[TPT], ta[TPT];
    const float* pj[TPT];   // gather base: &s_prob[0][label]; row via imm offset
    {
        int4 lv = *(const int4*)(labels + tbase);
        pj[0] = &s_prob[0][0] + lv.x;
        pj[1] = &s_prob[0][0] + lv.y;
        pj[2] = &s_prob[0][0] + lv.z;
        pj[3] = &s_prob[0][0] + lv.w;
    }
    #pragma unroll
    for (int j = 0; j < TPT; j++) {
        float4 tb = *(const float4*)(tboxes + (size_t)(tbase + j) * 4);
        tcx[j] = tb.x; tcy[j] = tb.y;
        tw2[j] = 0.5f * tb.z;
        th2[j] = 0.5f * tb.w;
        ta[j]  = tb.z * tb.w;
    }
    __syncthreads();

    // ---- Phase 2: 8 rows x 4 targets per thread ----
    // Identity: with u = pcx-tcx, v = pw2-tw2, hw = pw2+tw2, m = max(|u|,|v|):
    //   intersection width = hw - m, enclosing width = hw + m,
    //   |pcx-tcx| = |u|, |pw-tw| = 2|v|  (exact).
    // cost = 5*(|ux|+|uy|) + 10*(|vx|+|vy|) + (2-prob) - 2*inter/uni - 2*uni/ea
    float* orow = out + (size_t)row0 * TT + tbase;
    #pragma unroll
    for (int r = 0; r < ROWS; r++) {
        const float4 cw = s_cw[r];           // LDS.128 broadcast
        const float  pa = s_pa[r];

        float res[TPT];
        #pragma unroll
        for (int j = 0; j < TPT; j++) {
            float ux = cw.x - tcx[j];
            float uy = cw.y - tcy[j];
            float vx = cw.z - tw2[j];
            float vy = cw.w - th2[j];
            float mx = fmaxf(fabsf(ux), fabsf(vx));
            float my = fmaxf(fabsf(uy), fabsf(vy));
            float hx = cw.z + tw2[j];
            float hy = cw.w + th2[j];
            float iw = fmaxf(hx - mx, 0.0f);
            float ih = fmaxf(hy - my, 0.0f);
            float ew = hx + mx;
            float eh = hy + my;
            float inter = iw * ih;
            float ea    = ew * eh;
            float uni   = (pa + ta[j]) - inter;
            float t1    = inter * frcp(uni);
            float t2    = uni   * frcp(ea);
            float s1 = fabsf(ux) + fabsf(uy);
            float s2 = fabsf(vx) + fabsf(vy);
            float pr = pj[j][r * PSTRIDE];   // LDS [R+imm], (2 - prob)
            res[j] = fmaf(5.0f, s1,
                     fmaf(10.0f, s2,
                     fmaf(-2.0f, t1,
                     fmaf(-2.0f, t2, pr))));
        }
        *(float4*)(orow + (size_t)r * TT) =
            make_float4(res[0], res[1], res[2], res[3]);
    }
}

extern "C" void kernel_launch(void* const* d_in, const int* in_sizes, int n_in,
                              void* d_out, int out_size) {
    const float* logits = (const float*)d_in[0];
    const float* pboxes = (const float*)d_in[1];
    const int*   labels = (const int*)  d_in[2];
    const float* tboxes = (const float*)d_in[3];
    float* out = (float*)d_out;
    matcher_kernel<<<dim3(GRIDX, GRIDY), NTHR>>>(logits, pboxes, labels, tboxes, out);
}

// round 7
// speedup vs baseline: 1.0919x; 1.0303x over previous
#include <cuda_runtime.h>
#include <cuda_bf16.h>

// class_logits [64,300,92] f32, pred_boxes [64,300,4] f32,
// tgt_labels [2048] i32, tgt_boxes [2048,4] f32  ->  out [64,300,2048] f32
#define BQ      19200
#define CC      92
#define TT      2048
#define ROWS    8
#define NTHR    256
#define TPT     4
#define TBLK    (NTHR * TPT)     // 1024
#define GRIDX   (BQ / ROWS)      // 2400
#define GRIDY   (TT / TBLK)      // 2
#define PT      12               // transposed prob stride (floats): 48B, 16B-aligned

typedef unsigned long long u64;

__device__ __forceinline__ float frcp(float x) {
    float y; asm("rcp.approx.f32 %0, %1;" : "=f"(y) : "f"(x)); return y;
}
__device__ __forceinline__ u64 pk(float lo, float hi) {
    u64 d; asm("mov.b64 %0, {%1, %2};" : "=l"(d) : "f"(lo), "f"(hi)); return d;
}
__device__ __forceinline__ void upk(u64 p, float& lo, float& hi) {
    asm("mov.b64 {%0, %1}, %2;" : "=f"(lo), "=f"(hi) : "l"(p));
}
__device__ __forceinline__ u64 addx2(u64 a, u64 b) {
    u64 d; asm("add.rn.f32x2 %0, %1, %2;" : "=l"(d) : "l"(a), "l"(b)); return d;
}

__global__ __launch_bounds__(NTHR, 3)
void matcher_kernel(const float* __restrict__ logits,
                    const float* __restrict__ pboxes,
                    const int*   __restrict__ labels,
                    const float* __restrict__ tboxes,
                    float*       __restrict__ out)
{
    __shared__ float  s_probT[CC][PT];   // [class][row], holds (2 - prob)
    __shared__ float2 s_cxy[ROWS];       // pcx, pcy
    __shared__ float2 s_wh[ROWS];        // pw/2, ph/2
    __shared__ float  s_pa[ROWS];        // pw*ph

    const int tid  = threadIdx.x;
    const int warp = tid >> 5;           // 0..7 -> softmax row
    const int lane = tid & 31;
    const int row0 = blockIdx.x * ROWS;

    // ---- Phase 1: per-row softmax (warp w -> row w); transposed store of (2-prob) ----
    {
        const int rr = row0 + warp;
        const float* lrow = logits + (size_t)rr * CC;
        float l0 = lrow[lane];
        float l1 = lrow[lane + 32];
        float l2 = (lane + 64 < CC) ? lrow[lane + 64] : -1e30f;
        float m = fmaxf(l0, fmaxf(l1, l2));
        #pragma unroll
        for (int o = 16; o; o >>= 1) m = fmaxf(m, __shfl_xor_sync(0xffffffffu, m, o));
        float e0 = __expf(l0 - m);
        float e1 = __expf(l1 - m);
        float e2 = (lane + 64 < CC) ? __expf(l2 - m) : 0.0f;
        float s = e0 + e1 + e2;
        #pragma unroll
        for (int o = 16; o; o >>= 1) s += __shfl_xor_sync(0xffffffffu, s, o);
        float rinv = frcp(s);
        s_probT[lane][warp]      = fmaf(-e0, rinv, 2.0f);
        s_probT[lane + 32][warp] = fmaf(-e1, rinv, 2.0f);
        if (lane + 64 < CC) s_probT[lane + 64][warp] = fmaf(-e2, rinv, 2.0f);

        if (lane == 0) {
            float4 pb = *(const float4*)(pboxes + (size_t)rr * 4);
            s_cxy[warp] = make_float2(pb.x, pb.y);
            s_wh[warp]  = make_float2(0.5f * pb.z, 0.5f * pb.w);
            s_pa[warp]  = pb.z * pb.w;
        }
    }

    // ---- Phase 1b: targets -> packed registers (negated for packed adds) ----
    const int tbase = blockIdx.y * TBLK + tid * TPT;
    u64 ntc[TPT], nwh[TPT], pwh[TPT];
    float ta[TPT];
    const float* prp[TPT];
    {
        int4 lv = *(const int4*)(labels + tbase);
        prp[0] = &s_probT[lv.x][0];
        prp[1] = &s_probT[lv.y][0];
        prp[2] = &s_probT[lv.z][0];
        prp[3] = &s_probT[lv.w][0];
    }
    #pragma unroll
    for (int j = 0; j < TPT; j++) {
        float4 tb = *(const float4*)(tboxes + (size_t)(tbase + j) * 4);
        float w2 = 0.5f * tb.z, h2 = 0.5f * tb.w;
        ntc[j] = pk(-tb.x, -tb.y);
        nwh[j] = pk(-w2, -h2);
        pwh[j] = pk(w2, h2);
        ta[j]  = tb.z * tb.w;
    }
    __syncthreads();

    // probs for rows 0..3, all 4 targets (one LDS.128 each)
    float4 pra[TPT];
    #pragma unroll
    for (int j = 0; j < TPT; j++) pra[j] = *(const float4*)prp[j];

    // ---- Phase 2 ----
    // Identity: u=c_p-c_t, v=w2_p-w2_t, h=w2_p+w2_t, m=max(|u|,|v|)
    //   intersect width = h-m, enclose width = h+m, |dc|=|u|, |dw|=2|v|
    // cost = 5(|ux|+|uy|) + 10(|vx|+|vy|) + (2-prob) - 2*inter/uni - 2*uni/ea
    float* const obase = out + (size_t)row0 * TT + tbase;

#define BODY(r, PRSEL)                                                          \
    {                                                                           \
        float2 cxy = s_cxy[r];                                                  \
        float2 wh  = s_wh[r];                                                   \
        float  pa  = s_pa[r];                                                   \
        u64 cxyp = pk(cxy.x, cxy.y);                                            \
        u64 whp  = pk(wh.x, wh.y);                                              \
        float res[TPT];                                                         \
        _Pragma("unroll")                                                       \
        for (int j = 0; j < TPT; j++) {                                         \
            float ux, uy, vx, vy, hx, hy, iwx, iwy;                             \
            upk(addx2(cxyp, ntc[j]), ux, uy);                                   \
            upk(addx2(whp,  nwh[j]), vx, vy);                                   \
            upk(addx2(whp,  pwh[j]), hx, hy);                                   \
            float nmx = fminf(-fabsf(ux), -fabsf(vx));                          \
            float nmy = fminf(-fabsf(uy), -fabsf(vy));                          \
            upk(addx2(pk(hx, hy), pk(nmx, nmy)), iwx, iwy);                     \
            float iw = fmaxf(iwx, 0.0f);                                        \
            float ih = fmaxf(iwy, 0.0f);                                        \
            float ex = hx - nmx;                                                \
            float ey = hy - nmy;                                                \
            float inter = iw * ih;                                              \
            float ea    = ex * ey;                                              \
            float uni   = (pa + ta[j]) - inter;                                 \
            float t1    = inter * frcp(uni);                                    \
            float t2    = uni   * frcp(ea);                                     \
            float s1 = fabsf(ux) + fabsf(uy);                                   \
            float s2 = fabsf(vx) + fabsf(vy);                                   \
            float pr = PRSEL;                                                   \
            res[j] = fmaf(5.0f, s1, fmaf(10.0f, s2,                             \
                     fmaf(-2.0f, t1, fmaf(-2.0f, t2, pr))));                    \
        }                                                                       \
        *(float4*)(obase + (size_t)(r) * TT) =                                  \
            make_float4(res[0], res[1], res[2], res[3]);                        \
    }

    BODY(0, pra[j].x)
    BODY(1, pra[j].y)
    BODY(2, pra[j].z)
    BODY(3, pra[j].w)

    // probs for rows 4..7
    float4 prb[TPT];
    #pragma unroll
    for (int j = 0; j < TPT; j++) prb[j] = *(const float4*)(prp[j] + 4);

    BODY(4, prb[j].x)
    BODY(5, prb[j].y)
    BODY(6, prb[j].z)
    BODY(7, prb[j].w)
#undef BODY
}

extern "C" void kernel_launch(void* const* d_in, const int* in_sizes, int n_in,
                              void* d_out, int out_size) {
    const float* logits = (const float*)d_in[0];
    const float* pboxes = (const float*)d_in[1];
    const int*   labels = (const int*)  d_in[2];
    const float* tboxes = (const float*)d_in[3];
    float* out = (float*)d_out;
    matcher_kernel<<<dim3(GRIDX, GRIDY), NTHR>>>(logits, pboxes, labels, tboxes, out);
}